// round 8
// baseline (speedup 1.0000x reference)
#include <cuda_runtime.h>

// ============================================================================
// HybridLoss: B=2, T=4, N=4096  —  ONE launch, two block roles.
//   blockIdx.x <  128 : dist blocks (64 rows x 2048 cols tile, round-6 body)
//   blockIdx.x == 128 : per-bt epilogue block, spin-waits on arrival counter
// u(n,m) = (|p_n|^2 + rowBias_n) + (|t_m|^2 + colBias_m) - 2*dot(p_n,t_m)
// row-min(u) -> min_p (exact for valid rows), col-min(u) -> min_t (valid cols)
// Mins via RED.MAX on a descending order-isomorphic uint key (0 == +inf).
// All device state is zero at load and re-zeroed each call (graph-safe).
// ============================================================================

#define ALPHA_C  0.5f
#define INV_TEMP 10.0f
#define BIGF     10000000000.0f
#define THRESHF  1000000000.0f

constexpr int N_  = 4096;
constexpr int BT_ = 8;

constexpr int RPT      = 8;
constexpr int CPT      = 8;
constexpr int ROWS_BLK = 64;
constexpr int COLS_BLK = 2048;
constexpr int CCH      = 128;
constexpr int NCHUNKS  = COLS_BLK / CCH;     // 16
constexpr int ROWBLKS  = N_ / ROWS_BLK;      // 64
constexpr int COLBLKS  = N_ / COLS_BLK;      // 2
constexpr int BLOCKS_PER_BT = ROWBLKS * COLBLKS;  // 128

__device__ unsigned g_enc_p[BT_][N_];
__device__ unsigned g_enc_t[BT_][N_];
__device__ float    g_cd[BT_];
__device__ float    g_hd[BT_];
__device__ unsigned g_done_bt[BT_];
__device__ unsigned g_done;

// ---------------------------------------------------------------------------
__device__ __forceinline__ unsigned enc_desc(float f) {
    unsigned b = __float_as_uint(f);
    unsigned asc = (b & 0x80000000u) ? ~b : (b | 0x80000000u);
    return ~asc;
}
__device__ __forceinline__ float dec_desc(unsigned k) {
    unsigned asc = ~k;
    unsigned b = (asc & 0x80000000u) ? (asc ^ 0x80000000u) : ~asc;
    return __uint_as_float(b);
}

typedef unsigned long long u64;
__device__ __forceinline__ u64 fma2(u64 a, u64 b, u64 c) {
    u64 d; asm("fma.rn.f32x2 %0, %1, %2, %3;" : "=l"(d) : "l"(a), "l"(b), "l"(c));
    return d;
}
__device__ __forceinline__ u64 add2(u64 a, u64 b) {
    u64 d; asm("add.rn.f32x2 %0, %1, %2;" : "=l"(d) : "l"(a), "l"(b));
    return d;
}
__device__ __forceinline__ u64 pack2(float a, float b) {
    u64 r; asm("mov.b64 %0, {%1, %2};" : "=l"(r) : "f"(a), "f"(b));
    return r;
}
__device__ __forceinline__ void unpack2(u64 v, float& a, float& b) {
    asm("mov.b64 {%0, %1}, %2;" : "=f"(a), "=f"(b) : "l"(v));
}

__device__ __forceinline__ bool ldmask(const void* p, int i, int mode) {
    if (mode == 0) return ((const unsigned char*)p)[i] != 0;
    if (mode == 1) return ((const int*)p)[i] != 0;
    return ((const float*)p)[i] != 0.0f;
}

// Per-block mask-dtype detection (warp-0 ballot of 32 samples of the ~95%-
// dense padding mask). P(all 32 sampled bytes zero for u8 bool) ~ 0.05^32.
__device__ __forceinline__ int detect_mode_block(const unsigned char* pad,
                                                 int tid, int* s_mode) {
    if (tid < 32) {
        const unsigned b1 = __ballot_sync(0xffffffffu, pad[4 * tid + 1] != 0);
        const unsigned b2 = __ballot_sync(0xffffffffu, pad[4 * tid + 2] != 0);
        if (tid == 0) *s_mode = b1 ? 0 : (b2 ? 2 : 1);
    }
    __syncthreads();
    return *s_mode;
}

// 128-thread block reduction (4 warps).
__device__ __forceinline__ float blockRed128(float v, float* s, bool ismax) {
    const int w = threadIdx.x >> 5, l = threadIdx.x & 31;
#pragma unroll
    for (int o = 16; o > 0; o >>= 1) {
        const float x = __shfl_xor_sync(0xffffffffu, v, o);
        v = ismax ? fmaxf(v, x) : (v + x);
    }
    __syncthreads();
    if (l == 0) s[w] = v;
    __syncthreads();
    if (w == 0 && l == 0) {
        v = ismax ? fmaxf(fmaxf(s[0], s[1]), fmaxf(s[2], s[3]))
                  : ((s[0] + s[1]) + (s[2] + s[3]));
        s[0] = v;
    }
    __syncthreads();
    const float r = s[0];
    __syncthreads();
    return r;
}

// ---------------------------------------------------------------------------
__global__ void __launch_bounds__(128) hybrid_kernel(
    const float* __restrict__ pred, const float* __restrict__ tgt,
    const void* __restrict__ isctl, const void* __restrict__ pad,
    const void* __restrict__ vis, float* __restrict__ out)
{
    __shared__ float4 sc[CCH * 2];
    __shared__ int    s_mode;
    __shared__ float  s_red[4];

    const int bt   = blockIdx.y;
    const int b    = bt >> 2;
    const int tid  = threadIdx.x;
    const int mode = detect_mode_block((const unsigned char*)pad, tid, &s_mode);

    // ========================= EPILOGUE ROLE ===============================
    if (blockIdx.x == BLOCKS_PER_BT) {
        // wait for all 128 dist blocks of this bt
        if (tid == 0) {
            while (atomicAdd(&g_done_bt[bt], 0u) < (unsigned)BLOCKS_PER_BT)
                __nanosleep(128);
            g_done_bt[bt] = 0u;          // reset for the next call
        }
        __syncthreads();
        __threadfence();                  // acquire published mins

        constexpr int K = N_ / 128;       // 32 entries per thread
        float nv = 0.f, cdp = 0.f, cdt = 0.f;
        float mxp = -3.0e38f, mxt = -3.0e38f;
#pragma unroll 4
        for (int k = 0; k < K; k++) {
            const int n = tid + k * 128;
            const bool msk = !ldmask(isctl, b * N_ + n, mode)
                           &&  ldmask(pad,   b * N_ + n, mode)
                           &&  ldmask(vis,  bt * N_ + n, mode);
            if (msk) {
                const float mp = fmaxf(dec_desc(g_enc_p[bt][n]), 0.0f);
                const float mt = fmaxf(dec_desc(g_enc_t[bt][n]), 0.0f);
                nv  += 1.0f;
                cdp += (mp > THRESHF) ? 0.0f : mp;
                cdt += (mt > THRESHF) ? 0.0f : mt;
                mxp = fmaxf(mxp, fminf(mp, THRESHF));
                mxt = fmaxf(mxt, fminf(mt, THRESHF));
            }
        }
        const float nvT  = blockRed128(nv,  s_red, false);
        const float cdpT = blockRed128(cdp, s_red, false);
        const float cdtT = blockRed128(cdt, s_red, false);
        const float Mp   = blockRed128(mxp, s_red, true);
        const float Mt   = blockRed128(mxt, s_red, true);
        const bool  anyv = (Mp > -1.0e30f);

        float sep = 0.f, shp = 0.f, set = 0.f, sht = 0.f;
#pragma unroll 4
        for (int k = 0; k < K; k++) {
            const int n = tid + k * 128;
            const bool msk = !ldmask(isctl, b * N_ + n, mode)
                           &&  ldmask(pad,   b * N_ + n, mode)
                           &&  ldmask(vis,  bt * N_ + n, mode);
            const float mp = fmaxf(dec_desc(g_enc_p[bt][n]), 0.0f);
            const float mt = fmaxf(dec_desc(g_enc_t[bt][n]), 0.0f);
            g_enc_p[bt][n] = 0u;          // clean for next call
            g_enc_t[bt][n] = 0u;
            if (msk) {
                const float h1 = fminf(mp, THRESHF);
                const float h2 = fminf(mt, THRESHF);
                const float e1 = expf((h1 - Mp) * INV_TEMP);
                const float e2 = expf((h2 - Mt) * INV_TEMP);
                sep += e1; shp += h1 * e1;
                set += e2; sht += h2 * e2;
            }
        }
        const float sepT = blockRed128(sep, s_red, false);
        const float shpT = blockRed128(shp, s_red, false);
        const float setT = blockRed128(set, s_red, false);
        const float shtT = blockRed128(sht, s_red, false);

        if (tid == 0) {
            const float nvc = fmaxf(nvT, 1.0f);
            g_cd[bt] = cdpT / nvc + cdtT / nvc;
            const float rp = anyv ? (shpT / sepT) : 0.0f;
            const float rt = anyv ? (shtT / setT) : 0.0f;
            g_hd[bt] = fmaxf(rp, rt);
            __threadfence();
            const unsigned rank = atomicAdd(&g_done, 1u);
            if (rank == BT_ - 1) {        // final: fixed-order combine
                __threadfence();
                float cd = 0.f, hd = 0.f;
#pragma unroll
                for (int i = 0; i < BT_; i++) { cd += g_cd[i]; hd += g_hd[i]; }
                out[0] = ALPHA_C * (cd / (float)BT_)
                       + (1.0f - ALPHA_C) * (hd / (float)BT_);
                g_done = 0u;
            }
        }
        return;
    }

    // ========================== DIST ROLE ==================================
    const int rowblk = blockIdx.x >> 1;
    const int colblk = blockIdx.x & 1;
    const int tx     = tid >> 3;
    const int ty     = tid & 7;

    u64 px2[4], py2[4], pz2[4], rw2[4];
    float rmin[RPT];
    const int rbase = rowblk * ROWS_BLK + ty * RPT;
#pragma unroll
    for (int q = 0; q < 4; q++) {
        float x[2], y[2], z[2], w[2];
#pragma unroll
        for (int h = 0; h < 2; h++) {
            const int row = rbase + q * 2 + h;
            const float* rp = pred + ((size_t)bt * N_ + row) * 3;
            x[h] = rp[0]; y[h] = rp[1]; z[h] = rp[2];
            const bool msk = !ldmask(isctl, b * N_ + row, mode)
                           &&  ldmask(pad,   b * N_ + row, mode)
                           &&  ldmask(vis,  bt * N_ + row, mode);
            w[h] = fmaf(x[h], x[h], fmaf(y[h], y[h], z[h] * z[h]))
                 + (msk ? 0.0f : BIGF);
            rmin[q * 2 + h] = 3.0e38f;
        }
        px2[q] = pack2(x[0], x[1]);
        py2[q] = pack2(y[0], y[1]);
        pz2[q] = pack2(z[0], z[1]);
        rw2[q] = pack2(w[0], w[1]);
    }

    for (int chunk = 0; chunk < NCHUNKS; chunk++) {
        __syncthreads();
        {
            const int m = colblk * COLS_BLK + chunk * CCH + tid;
            const float* cp = tgt + ((size_t)bt * N_ + m) * 3;
            const float x = cp[0], y = cp[1], z = cp[2];
            const bool msk = !ldmask(isctl, b * N_ + m, mode)
                           &&  ldmask(pad,   b * N_ + m, mode)
                           &&  ldmask(vis,  bt * N_ + m, mode);
            const float cw = fmaf(x, x, fmaf(y, y, z * z))
                           + (msk ? 0.0f : BIGF);
            sc[2 * tid]     = make_float4(-2.f * x, -2.f * x, -2.f * y, -2.f * y);
            sc[2 * tid + 1] = make_float4(-2.f * z, -2.f * z, cw, cw);
        }
        __syncthreads();

        float cmin[CPT];
#pragma unroll
        for (int j = 0; j < CPT; j++) {
            const u64* cd = reinterpret_cast<const u64*>(&sc[2 * (tx * CPT + j)]);
            const u64 xd = cd[0], yd = cd[1], zd = cd[2], wd = cd[3];
            float cm = 3.0e38f;
#pragma unroll
            for (int q = 0; q < 4; q++) {
                const u64 acc = fma2(px2[q], xd,
                                fma2(py2[q], yd,
                                fma2(pz2[q], zd, add2(wd, rw2[q]))));
                float lo, hi;
                unpack2(acc, lo, hi);
                rmin[q * 2]     = fminf(rmin[q * 2], lo);
                rmin[q * 2 + 1] = fminf(rmin[q * 2 + 1], hi);
                cm = fminf(cm, fminf(lo, hi));
            }
            cmin[j] = cm;
        }

#pragma unroll
        for (int j = 0; j < CPT; j++) {
            cmin[j] = fminf(cmin[j], __shfl_xor_sync(0xffffffffu, cmin[j], 4));
            cmin[j] = fminf(cmin[j], __shfl_xor_sync(0xffffffffu, cmin[j], 2));
            cmin[j] = fminf(cmin[j], __shfl_xor_sync(0xffffffffu, cmin[j], 1));
        }
        if (ty == 0) {
            const int cbase = colblk * COLS_BLK + chunk * CCH + tx * CPT;
#pragma unroll
            for (int j = 0; j < CPT; j++)
                atomicMax(&g_enc_t[bt][cbase + j], enc_desc(cmin[j]));
        }
    }

#pragma unroll
    for (int r = 0; r < RPT; r++) {
        rmin[r] = fminf(rmin[r], __shfl_xor_sync(0xffffffffu, rmin[r], 8));
        rmin[r] = fminf(rmin[r], __shfl_xor_sync(0xffffffffu, rmin[r], 16));
    }
    if ((tid & 31) < 8) {
#pragma unroll
        for (int r = 0; r < RPT; r++)
            atomicMax(&g_enc_p[bt][rbase + r], enc_desc(rmin[r]));
    }

    // signal completion of this dist block (release ordering)
    __threadfence();
    __syncthreads();
    if (tid == 0) atomicAdd(&g_done_bt[bt], 1u);
}

// ---------------------------------------------------------------------------
extern "C" void kernel_launch(void* const* d_in, const int* in_sizes, int n_in,
                              void* d_out, int out_size) {
    const float* pred = (const float*)d_in[0];
    const float* tgt  = (const float*)d_in[1];
    const void*  isc  = d_in[2];
    const void*  pad  = d_in[3];
    const void*  vis  = d_in[4];

    hybrid_kernel<<<dim3(BLOCKS_PER_BT + 1, BT_), 128>>>(
        pred, tgt, isc, pad, vis, (float*)d_out);
}

// round 9
// speedup vs baseline: 1.3550x; 1.3550x over previous
#include <cuda_runtime.h>

// ============================================================================
// HybridLoss: B=2, T=4, N=4096  —  2 launches, decoupled register budgets.
//   dist:     grid (64,2,8) x 128 thr, __launch_bounds__(128,8)
//   epilogue: grid 8 x 256 thr, single-pass register-resident reduction
// u(n,m) = (|p_n|^2 + rowBias_n) + (|t_m|^2 + colBias_m) - 2*dot(p_n,t_m)
// row-min(u) -> min_p (exact for valid rows), col-min(u) -> min_t (valid cols)
// Mins via RED.MAX on a descending order-isomorphic uint key (0 == +inf).
// All device state zero at load and re-zeroed each call (graph-safe).
// ============================================================================

#define ALPHA_C  0.5f
#define INV_TEMP 10.0f
#define BIGF     10000000000.0f
#define THRESHF  1000000000.0f

constexpr int N_  = 4096;
constexpr int BT_ = 8;

constexpr int RPT      = 8;
constexpr int CPT      = 8;
constexpr int ROWS_BLK = 64;
constexpr int COLS_BLK = 2048;
constexpr int CCH      = 128;
constexpr int NCHUNKS  = COLS_BLK / CCH;     // 16
constexpr int ROWBLKS  = N_ / ROWS_BLK;      // 64
constexpr int COLBLKS  = N_ / COLS_BLK;      // 2

__device__ unsigned g_enc_p[BT_][N_];
__device__ unsigned g_enc_t[BT_][N_];
__device__ float    g_cd[BT_];
__device__ float    g_hd[BT_];
__device__ unsigned g_done;

// ---------------------------------------------------------------------------
__device__ __forceinline__ unsigned enc_desc(float f) {
    unsigned b = __float_as_uint(f);
    unsigned asc = (b & 0x80000000u) ? ~b : (b | 0x80000000u);
    return ~asc;
}
__device__ __forceinline__ float dec_desc(unsigned k) {
    unsigned asc = ~k;
    unsigned b = (asc & 0x80000000u) ? (asc ^ 0x80000000u) : ~asc;
    return __uint_as_float(b);
}

typedef unsigned long long u64;
__device__ __forceinline__ u64 fma2(u64 a, u64 b, u64 c) {
    u64 d; asm("fma.rn.f32x2 %0, %1, %2, %3;" : "=l"(d) : "l"(a), "l"(b), "l"(c));
    return d;
}
__device__ __forceinline__ u64 add2(u64 a, u64 b) {
    u64 d; asm("add.rn.f32x2 %0, %1, %2;" : "=l"(d) : "l"(a), "l"(b));
    return d;
}
__device__ __forceinline__ u64 pack2(float a, float b) {
    u64 r; asm("mov.b64 %0, {%1, %2};" : "=l"(r) : "f"(a), "f"(b));
    return r;
}
__device__ __forceinline__ void unpack2(u64 v, float& a, float& b) {
    asm("mov.b64 {%0, %1}, %2;" : "=f"(a), "=f"(b) : "l"(v));
}

__device__ __forceinline__ bool ldmask(const void* p, int i, int mode) {
    if (mode == 0) return ((const unsigned char*)p)[i] != 0;
    if (mode == 1) return ((const int*)p)[i] != 0;
    return ((const float*)p)[i] != 0.0f;
}

// Per-block mask-dtype detection (warp-0 ballot of 32 samples of the ~95%-
// dense padding mask). P(all 32 sampled bytes zero for u8 bool) ~ 0.05^32.
__device__ __forceinline__ int detect_mode_block(const unsigned char* pad,
                                                 int tid, int* s_mode) {
    if (tid < 32) {
        const unsigned b1 = __ballot_sync(0xffffffffu, pad[4 * tid + 1] != 0);
        const unsigned b2 = __ballot_sync(0xffffffffu, pad[4 * tid + 2] != 0);
        if (tid == 0) *s_mode = b1 ? 0 : (b2 ? 2 : 1);
    }
    __syncthreads();
    return *s_mode;
}

// ---------------------------------------------------------------------------
// dist: grid (ROWBLKS, COLBLKS, BT_), 128 threads, min 8 blocks/SM.
// tid = tx*8 + ty  (tx 0..15 col group, ty 0..7 -> 8 consecutive rows)
// ---------------------------------------------------------------------------
__global__ void __launch_bounds__(128, 8) dist_kernel(
    const float* __restrict__ pred, const float* __restrict__ tgt,
    const void* __restrict__ isctl, const void* __restrict__ pad,
    const void* __restrict__ vis)
{
    __shared__ float4 sc[CCH * 2];   // per col: (-2x,-2x,-2y,-2y)(-2z,-2z,w,w)
    __shared__ int    s_mode;

    const int rowblk = blockIdx.x;
    const int colblk = blockIdx.y;
    const int bt     = blockIdx.z;
    const int b      = bt >> 2;
    const int tid    = threadIdx.x;
    const int tx     = tid >> 3;
    const int ty     = tid & 7;
    const int mode   = detect_mode_block((const unsigned char*)pad, tid, &s_mode);

    u64 px2[4], py2[4], pz2[4], rw2[4];
    float rmin[RPT];
    const int rbase = rowblk * ROWS_BLK + ty * RPT;
#pragma unroll
    for (int q = 0; q < 4; q++) {
        float x[2], y[2], z[2], w[2];
#pragma unroll
        for (int h = 0; h < 2; h++) {
            const int row = rbase + q * 2 + h;
            const float* rp = pred + ((size_t)bt * N_ + row) * 3;
            x[h] = rp[0]; y[h] = rp[1]; z[h] = rp[2];
            const bool msk = !ldmask(isctl, b * N_ + row, mode)
                           &&  ldmask(pad,   b * N_ + row, mode)
                           &&  ldmask(vis,  bt * N_ + row, mode);
            w[h] = fmaf(x[h], x[h], fmaf(y[h], y[h], z[h] * z[h]))
                 + (msk ? 0.0f : BIGF);
            rmin[q * 2 + h] = 3.0e38f;
        }
        px2[q] = pack2(x[0], x[1]);
        py2[q] = pack2(y[0], y[1]);
        pz2[q] = pack2(z[0], z[1]);
        rw2[q] = pack2(w[0], w[1]);
    }

    for (int chunk = 0; chunk < NCHUNKS; chunk++) {
        __syncthreads();
        {
            const int m = colblk * COLS_BLK + chunk * CCH + tid;
            const float* cp = tgt + ((size_t)bt * N_ + m) * 3;
            const float x = cp[0], y = cp[1], z = cp[2];
            const bool msk = !ldmask(isctl, b * N_ + m, mode)
                           &&  ldmask(pad,   b * N_ + m, mode)
                           &&  ldmask(vis,  bt * N_ + m, mode);
            const float cw = fmaf(x, x, fmaf(y, y, z * z))
                           + (msk ? 0.0f : BIGF);
            sc[2 * tid]     = make_float4(-2.f * x, -2.f * x, -2.f * y, -2.f * y);
            sc[2 * tid + 1] = make_float4(-2.f * z, -2.f * z, cw, cw);
        }
        __syncthreads();

        float cmin[CPT];
#pragma unroll
        for (int j = 0; j < CPT; j++) {
            const u64* cd = reinterpret_cast<const u64*>(&sc[2 * (tx * CPT + j)]);
            const u64 xd = cd[0], yd = cd[1], zd = cd[2], wd = cd[3];
            float cm = 3.0e38f;
#pragma unroll
            for (int q = 0; q < 4; q++) {
                const u64 acc = fma2(px2[q], xd,
                                fma2(py2[q], yd,
                                fma2(pz2[q], zd, add2(wd, rw2[q]))));
                float lo, hi;
                unpack2(acc, lo, hi);
                rmin[q * 2]     = fminf(rmin[q * 2], lo);
                rmin[q * 2 + 1] = fminf(rmin[q * 2 + 1], hi);
                cm = fminf(cm, fminf(lo, hi));
            }
            cmin[j] = cm;
        }

        // col-min across the 8 ty-lanes of each tx octet
#pragma unroll
        for (int j = 0; j < CPT; j++) {
            cmin[j] = fminf(cmin[j], __shfl_xor_sync(0xffffffffu, cmin[j], 4));
            cmin[j] = fminf(cmin[j], __shfl_xor_sync(0xffffffffu, cmin[j], 2));
            cmin[j] = fminf(cmin[j], __shfl_xor_sync(0xffffffffu, cmin[j], 1));
        }
        if (ty == 0) {
            const int cbase = colblk * COLS_BLK + chunk * CCH + tx * CPT;
#pragma unroll
            for (int j = 0; j < CPT; j++)
                atomicMax(&g_enc_t[bt][cbase + j], enc_desc(cmin[j]));
        }
    }

#pragma unroll
    for (int r = 0; r < RPT; r++) {
        rmin[r] = fminf(rmin[r], __shfl_xor_sync(0xffffffffu, rmin[r], 8));
        rmin[r] = fminf(rmin[r], __shfl_xor_sync(0xffffffffu, rmin[r], 16));
    }
    if ((tid & 31) < 8) {
#pragma unroll
        for (int r = 0; r < RPT; r++)
            atomicMax(&g_enc_p[bt][rbase + r], enc_desc(rmin[r]));
    }
}

// ---------------------------------------------------------------------------
// epilogue: grid=8 (bt), 256 threads, SINGLE global pass (values kept in
// registers), re-zeroes scratch, fixed-order final combine via g_done.
// ---------------------------------------------------------------------------
__device__ __forceinline__ float blockRed256(float v, float* s, bool ismax) {
    const int w = threadIdx.x >> 5, l = threadIdx.x & 31;
#pragma unroll
    for (int o = 16; o > 0; o >>= 1) {
        const float x = __shfl_xor_sync(0xffffffffu, v, o);
        v = ismax ? fmaxf(v, x) : (v + x);
    }
    __syncthreads();
    if (l == 0) s[w] = v;
    __syncthreads();
    if (w == 0) {
        v = s[l & 7];
#pragma unroll
        for (int o = 4; o > 0; o >>= 1) {
            const float x = __shfl_xor_sync(0xffffffffu, v, o);
            v = ismax ? fmaxf(v, x) : (v + x);
        }
        if (l == 0) s[0] = v;
    }
    __syncthreads();
    const float r = s[0];
    __syncthreads();
    return r;
}

__global__ void __launch_bounds__(256) epilogue_kernel(
    const void* __restrict__ isctl, const void* __restrict__ pad,
    const void* __restrict__ vis, float* __restrict__ out)
{
    __shared__ float s[8];
    __shared__ int   s_mode;
    const int bt   = blockIdx.x;
    const int b    = bt >> 2;
    const int tid  = threadIdx.x;
    const int mode = detect_mode_block((const unsigned char*)pad, tid, &s_mode);
    constexpr int K = N_ / 256;   // 16

    float hp[K], ht[K];
    bool  mk[K];
    float nv = 0.f, cdp = 0.f, cdt = 0.f;
    float mxp = -3.0e38f, mxt = -3.0e38f;

    // single global pass: read mins, re-zero, compute everything register-side
#pragma unroll
    for (int k = 0; k < K; k++) {
        const int n = tid + k * 256;
        const bool msk = !ldmask(isctl, b * N_ + n, mode)
                       &&  ldmask(pad,   b * N_ + n, mode)
                       &&  ldmask(vis,  bt * N_ + n, mode);
        mk[k] = msk;
        const float mp = fmaxf(dec_desc(g_enc_p[bt][n]), 0.0f);
        const float mt = fmaxf(dec_desc(g_enc_t[bt][n]), 0.0f);
        g_enc_p[bt][n] = 0u;                  // clean for the next call
        g_enc_t[bt][n] = 0u;
        if (msk) {
            nv  += 1.0f;
            cdp += (mp > THRESHF) ? 0.0f : mp;
            cdt += (mt > THRESHF) ? 0.0f : mt;
            hp[k] = fminf(mp, THRESHF);
            ht[k] = fminf(mt, THRESHF);
            mxp = fmaxf(mxp, hp[k]);
            mxt = fmaxf(mxt, ht[k]);
        } else { hp[k] = 0.f; ht[k] = 0.f; }
    }

    const float nvT  = blockRed256(nv,  s, false);
    const float cdpT = blockRed256(cdp, s, false);
    const float cdtT = blockRed256(cdt, s, false);
    const float Mp   = blockRed256(mxp, s, true);
    const float Mt   = blockRed256(mxt, s, true);
    const bool  anyv = (Mp > -1.0e30f);

    // softmax sums from registers (masked-out entries contribute exactly 0)
    float sep = 0.f, shp = 0.f, set = 0.f, sht = 0.f;
#pragma unroll
    for (int k = 0; k < K; k++) {
        if (mk[k]) {
            const float e1 = expf((hp[k] - Mp) * INV_TEMP);
            const float e2 = expf((ht[k] - Mt) * INV_TEMP);
            sep += e1; shp += hp[k] * e1;
            set += e2; sht += ht[k] * e2;
        }
    }
    const float sepT = blockRed256(sep, s, false);
    const float shpT = blockRed256(shp, s, false);
    const float setT = blockRed256(set, s, false);
    const float shtT = blockRed256(sht, s, false);

    if (tid == 0) {
        const float nvc = fmaxf(nvT, 1.0f);
        g_cd[bt] = cdpT / nvc + cdtT / nvc;
        const float rp = anyv ? (shpT / sepT) : 0.0f;
        const float rt = anyv ? (shtT / setT) : 0.0f;
        g_hd[bt] = fmaxf(rp, rt);
        __threadfence();
        const unsigned rank = atomicAdd(&g_done, 1u);
        if (rank == BT_ - 1) {                // last block: fixed-order combine
            __threadfence();
            float cd = 0.f, hd = 0.f;
#pragma unroll
            for (int i = 0; i < BT_; i++) { cd += g_cd[i]; hd += g_hd[i]; }
            out[0] = ALPHA_C * (cd / (float)BT_)
                   + (1.0f - ALPHA_C) * (hd / (float)BT_);
            g_done = 0u;                      // reset for next call
        }
    }
}

// ---------------------------------------------------------------------------
extern "C" void kernel_launch(void* const* d_in, const int* in_sizes, int n_in,
                              void* d_out, int out_size) {
    const float* pred = (const float*)d_in[0];
    const float* tgt  = (const float*)d_in[1];
    const void*  isc  = d_in[2];
    const void*  pad  = d_in[3];
    const void*  vis  = d_in[4];

    dist_kernel<<<dim3(ROWBLKS, COLBLKS, BT_), 128>>>(pred, tgt, isc, pad, vis);
    epilogue_kernel<<<BT_, 256>>>(isc, pad, vis, (float*)d_out);
}

// round 10
// speedup vs baseline: 1.6193x; 1.1951x over previous
#include <cuda_runtime.h>

// ============================================================================
// HybridLoss: B=2, T=4, N=4096  —  2 launches.
// DIST (dual-pass, zero-shuffle): block = 512 rows x 512 cols, 128 threads.
//   pass 0: rows=pred, cols=tgt  -> row-min = min_p -> g_enc_p
//   pass 1: rows=tgt,  cols=pred -> row-min = min_t -> g_enc_t
//   Columns staged ONCE in smem (duplicated packed layout); after one barrier
//   the loop is a pure LDS+FFMA2 stream; each thread owns 4 rows exclusively
//   (no shuffles), publishing via atomicMax on a descending-ordered uint key.
// EPILOGUE: grid 8 x 1024 thr, single global pass, self-cleaning, g_done
//   fixed-order combine into out[0]. All state zero at load & after each call.
// ============================================================================

#define ALPHA_C  0.5f
#define INV_TEMP 10.0f
#define BIGF     10000000000.0f
#define THRESHF  1000000000.0f

constexpr int N_  = 4096;
constexpr int BT_ = 8;

constexpr int ROWS_PB = 512;              // rows per block
constexpr int COLS_PB = 512;              // cols per block (staged once)
constexpr int RPT     = 4;                // rows per thread (2 packed pairs)
constexpr int ROWBLKS = N_ / ROWS_PB;     // 8
constexpr int COLBLKS = N_ / COLS_PB;     // 8

__device__ unsigned g_enc_p[BT_][N_];
__device__ unsigned g_enc_t[BT_][N_];
__device__ float    g_cd[BT_];
__device__ float    g_hd[BT_];
__device__ unsigned g_done;

// ---------------------------------------------------------------------------
__device__ __forceinline__ unsigned enc_desc(float f) {
    unsigned b = __float_as_uint(f);
    unsigned asc = (b & 0x80000000u) ? ~b : (b | 0x80000000u);
    return ~asc;
}
__device__ __forceinline__ float dec_desc(unsigned k) {
    unsigned asc = ~k;
    unsigned b = (asc & 0x80000000u) ? (asc ^ 0x80000000u) : ~asc;
    return __uint_as_float(b);
}

typedef unsigned long long u64;
__device__ __forceinline__ u64 fma2(u64 a, u64 b, u64 c) {
    u64 d; asm("fma.rn.f32x2 %0, %1, %2, %3;" : "=l"(d) : "l"(a), "l"(b), "l"(c));
    return d;
}
__device__ __forceinline__ u64 add2(u64 a, u64 b) {
    u64 d; asm("add.rn.f32x2 %0, %1, %2;" : "=l"(d) : "l"(a), "l"(b));
    return d;
}
__device__ __forceinline__ u64 pack2(float a, float b) {
    u64 r; asm("mov.b64 %0, {%1, %2};" : "=l"(r) : "f"(a), "f"(b));
    return r;
}
__device__ __forceinline__ void unpack2(u64 v, float& a, float& b) {
    asm("mov.b64 {%0, %1}, %2;" : "=f"(a), "=f"(b) : "l"(v));
}

__device__ __forceinline__ bool ldmask(const void* p, int i, int mode) {
    if (mode == 0) return ((const unsigned char*)p)[i] != 0;
    if (mode == 1) return ((const int*)p)[i] != 0;
    return ((const float*)p)[i] != 0.0f;
}

// Per-block mask-dtype detection (warp-0 ballot of 32 samples of the ~95%-
// dense padding mask). P(all 32 sampled bytes zero for u8 bool) ~ 0.05^32.
__device__ __forceinline__ int detect_mode_block(const unsigned char* pad,
                                                 int tid, int* s_mode) {
    if (tid < 32) {
        const unsigned b1 = __ballot_sync(0xffffffffu, pad[4 * tid + 1] != 0);
        const unsigned b2 = __ballot_sync(0xffffffffu, pad[4 * tid + 2] != 0);
        if (tid == 0) *s_mode = b1 ? 0 : (b2 ? 2 : 1);
    }
    __syncthreads();
    return *s_mode;
}

// ---------------------------------------------------------------------------
// dist: grid (ROWBLKS, COLBLKS, BT_*2), 128 threads.
// ---------------------------------------------------------------------------
__global__ void __launch_bounds__(128) dist_kernel(
    const float* __restrict__ pred, const float* __restrict__ tgt,
    const void* __restrict__ isctl, const void* __restrict__ pad,
    const void* __restrict__ vis)
{
    __shared__ float4 sc[COLS_PB * 2];  // per col: (-2x,-2x,-2y,-2y)(-2z,-2z,w,w)
    __shared__ int    s_mode;

    const int rowblk = blockIdx.x;
    const int colblk = blockIdx.y;
    const int bt     = blockIdx.z >> 1;
    const int pass   = blockIdx.z & 1;
    const int b      = bt >> 2;
    const int tid    = threadIdx.x;
    const int mode   = detect_mode_block((const unsigned char*)pad, tid, &s_mode);

    const float* __restrict__ rows = pass ? tgt  : pred;
    const float* __restrict__ cols = pass ? pred : tgt;
    unsigned* __restrict__ enc = pass ? &g_enc_t[bt][0] : &g_enc_p[bt][0];

    // ---- stage this block's 512 columns (once) -----------------------------
#pragma unroll
    for (int c = tid; c < COLS_PB; c += 128) {
        const int m = colblk * COLS_PB + c;
        const float* cp = cols + ((size_t)bt * N_ + m) * 3;
        const float x = cp[0], y = cp[1], z = cp[2];
        const bool msk = !ldmask(isctl, b * N_ + m, mode)
                       &&  ldmask(pad,   b * N_ + m, mode)
                       &&  ldmask(vis,  bt * N_ + m, mode);
        const float cw = fmaf(x, x, fmaf(y, y, z * z)) + (msk ? 0.0f : BIGF);
        sc[2 * c]     = make_float4(-2.f * x, -2.f * x, -2.f * y, -2.f * y);
        sc[2 * c + 1] = make_float4(-2.f * z, -2.f * z, cw, cw);
    }

    // ---- this thread's 4 rows (2 packed pairs) -----------------------------
    u64 px2[2], py2[2], pz2[2], rw2[2];
    float rmin[RPT];
    const int rbase = rowblk * ROWS_PB + tid * RPT;
#pragma unroll
    for (int q = 0; q < 2; q++) {
        float x[2], y[2], z[2], w[2];
#pragma unroll
        for (int h = 0; h < 2; h++) {
            const int row = rbase + q * 2 + h;
            const float* rp = rows + ((size_t)bt * N_ + row) * 3;
            x[h] = rp[0]; y[h] = rp[1]; z[h] = rp[2];
            const bool msk = !ldmask(isctl, b * N_ + row, mode)
                           &&  ldmask(pad,   b * N_ + row, mode)
                           &&  ldmask(vis,  bt * N_ + row, mode);
            w[h] = fmaf(x[h], x[h], fmaf(y[h], y[h], z[h] * z[h]))
                 + (msk ? 0.0f : BIGF);
            rmin[q * 2 + h] = 3.0e38f;
        }
        px2[q] = pack2(x[0], x[1]);
        py2[q] = pack2(y[0], y[1]);
        pz2[q] = pack2(z[0], z[1]);
        rw2[q] = pack2(w[0], w[1]);
    }
    __syncthreads();   // the only barrier

    // ---- pure streaming loop: 512 cols x 4 rows ----------------------------
#pragma unroll 4
    for (int c = 0; c < COLS_PB; c++) {
        const u64* cd = reinterpret_cast<const u64*>(&sc[2 * c]);
        const u64 xd = cd[0], yd = cd[1], zd = cd[2], wd = cd[3];
#pragma unroll
        for (int q = 0; q < 2; q++) {
            const u64 acc = fma2(px2[q], xd,
                            fma2(py2[q], yd,
                            fma2(pz2[q], zd, add2(wd, rw2[q]))));
            float lo, hi;
            unpack2(acc, lo, hi);
            rmin[q * 2]     = fminf(rmin[q * 2], lo);
            rmin[q * 2 + 1] = fminf(rmin[q * 2 + 1], hi);
        }
    }

    // ---- publish 4 row-mins (thread-exclusive rows, 8 colblk contenders) ---
#pragma unroll
    for (int r = 0; r < RPT; r++)
        atomicMax(&enc[rbase + r], enc_desc(rmin[r]));
}

// ---------------------------------------------------------------------------
// epilogue: grid=8 (bt), 1024 threads, single global pass, self-cleaning.
// ---------------------------------------------------------------------------
__device__ __forceinline__ float blockRed1024(float v, float* s, bool ismax) {
    const int w = threadIdx.x >> 5, l = threadIdx.x & 31;
#pragma unroll
    for (int o = 16; o > 0; o >>= 1) {
        const float x = __shfl_xor_sync(0xffffffffu, v, o);
        v = ismax ? fmaxf(v, x) : (v + x);
    }
    __syncthreads();
    if (l == 0) s[w] = v;
    __syncthreads();
    if (w == 0) {
        v = s[l];
#pragma unroll
        for (int o = 16; o > 0; o >>= 1) {
            const float x = __shfl_xor_sync(0xffffffffu, v, o);
            v = ismax ? fmaxf(v, x) : (v + x);
        }
        if (l == 0) s[0] = v;
    }
    __syncthreads();
    const float r = s[0];
    __syncthreads();
    return r;
}

__global__ void __launch_bounds__(1024) epilogue_kernel(
    const void* __restrict__ isctl, const void* __restrict__ pad,
    const void* __restrict__ vis, float* __restrict__ out)
{
    __shared__ float s[32];
    __shared__ int   s_mode;
    const int bt   = blockIdx.x;
    const int b    = bt >> 2;
    const int tid  = threadIdx.x;
    const int mode = detect_mode_block((const unsigned char*)pad, tid, &s_mode);
    constexpr int K = N_ / 1024;   // 4

    float hp[K], ht[K];
    bool  mk[K];
    float nv = 0.f, cdp = 0.f, cdt = 0.f;
    float mxp = -3.0e38f, mxt = -3.0e38f;

    // single global pass: read mins, re-zero scratch, fill register arrays
#pragma unroll
    for (int k = 0; k < K; k++) {
        const int n = tid + k * 1024;
        const bool msk = !ldmask(isctl, b * N_ + n, mode)
                       &&  ldmask(pad,   b * N_ + n, mode)
                       &&  ldmask(vis,  bt * N_ + n, mode);
        mk[k] = msk;
        const float mp = fmaxf(dec_desc(g_enc_p[bt][n]), 0.0f);
        const float mt = fmaxf(dec_desc(g_enc_t[bt][n]), 0.0f);
        g_enc_p[bt][n] = 0u;                  // clean for next call
        g_enc_t[bt][n] = 0u;
        if (msk) {
            nv  += 1.0f;
            cdp += (mp > THRESHF) ? 0.0f : mp;
            cdt += (mt > THRESHF) ? 0.0f : mt;
            hp[k] = fminf(mp, THRESHF);
            ht[k] = fminf(mt, THRESHF);
            mxp = fmaxf(mxp, hp[k]);
            mxt = fmaxf(mxt, ht[k]);
        } else { hp[k] = 0.f; ht[k] = 0.f; }
    }

    const float nvT  = blockRed1024(nv,  s, false);
    const float cdpT = blockRed1024(cdp, s, false);
    const float cdtT = blockRed1024(cdt, s, false);
    const float Mp   = blockRed1024(mxp, s, true);
    const float Mt   = blockRed1024(mxt, s, true);
    const bool  anyv = (Mp > -1.0e30f);

    // softmax sums from registers (masked-out entries contribute exactly 0)
    float sep = 0.f, shp = 0.f, set = 0.f, sht = 0.f;
#pragma unroll
    for (int k = 0; k < K; k++) {
        if (mk[k]) {
            const float e1 = expf((hp[k] - Mp) * INV_TEMP);
            const float e2 = expf((ht[k] - Mt) * INV_TEMP);
            sep += e1; shp += hp[k] * e1;
            set += e2; sht += ht[k] * e2;
        }
    }
    const float sepT = blockRed1024(sep, s, false);
    const float shpT = blockRed1024(shp, s, false);
    const float setT = blockRed1024(set, s, false);
    const float shtT = blockRed1024(sht, s, false);

    if (tid == 0) {
        const float nvc = fmaxf(nvT, 1.0f);
        g_cd[bt] = cdpT / nvc + cdtT / nvc;
        const float rp = anyv ? (shpT / sepT) : 0.0f;
        const float rt = anyv ? (shtT / setT) : 0.0f;
        g_hd[bt] = fmaxf(rp, rt);
        __threadfence();
        const unsigned rank = atomicAdd(&g_done, 1u);
        if (rank == BT_ - 1) {                // last block: fixed-order combine
            __threadfence();
            float cd = 0.f, hd = 0.f;
#pragma unroll
            for (int i = 0; i < BT_; i++) { cd += g_cd[i]; hd += g_hd[i]; }
            out[0] = ALPHA_C * (cd / (float)BT_)
                   + (1.0f - ALPHA_C) * (hd / (float)BT_);
            g_done = 0u;                      // reset for next call
        }
    }
}

// ---------------------------------------------------------------------------
extern "C" void kernel_launch(void* const* d_in, const int* in_sizes, int n_in,
                              void* d_out, int out_size) {
    const float* pred = (const float*)d_in[0];
    const float* tgt  = (const float*)d_in[1];
    const void*  isc  = d_in[2];
    const void*  pad  = d_in[3];
    const void*  vis  = d_in[4];

    dist_kernel<<<dim3(ROWBLKS, COLBLKS, BT_ * 2), 128>>>(
        pred, tgt, isc, pad, vis);
    epilogue_kernel<<<BT_, 1024>>>(isc, pad, vis, (float*)d_out);
}

// round 11
// speedup vs baseline: 1.6327x; 1.0083x over previous
#include <cuda_runtime.h>

// ============================================================================
// HybridLoss: B=2, T=4, N=4096  —  2 launches with PDL overlap.
// DIST (dual-pass, zero-shuffle): block = 1024 rows x 512 cols, 128 thr.
//   pass 0: rows=pred, cols=tgt  -> row-min = min_p -> g_enc_p
//   pass 1: rows=tgt,  cols=pred -> row-min = min_t -> g_enc_t
//   Columns staged ONCE in smem; pure LDS+FFMA2 stream; each thread owns
//   8 rows exclusively; publishes via atomicMax on desc-ordered uint key.
//   Executes griddepcontrol.launch_dependents at start (PDL).
// EPILOGUE: grid 8 x 1024 thr, PDL dependent: mask preamble BEFORE
//   griddepcontrol.wait, then min-dependent reduction. Self-cleaning state.
// ============================================================================

#define ALPHA_C  0.5f
#define INV_TEMP 10.0f
#define BIGF     10000000000.0f
#define THRESHF  1000000000.0f

constexpr int N_  = 4096;
constexpr int BT_ = 8;

constexpr int ROWS_PB = 1024;             // rows per block
constexpr int COLS_PB = 512;              // cols per block (staged once)
constexpr int RPT     = 8;                // rows per thread (4 packed pairs)
constexpr int ROWBLKS = N_ / ROWS_PB;     // 4
constexpr int COLBLKS = N_ / COLS_PB;     // 8

__device__ unsigned g_enc_p[BT_][N_];
__device__ unsigned g_enc_t[BT_][N_];
__device__ float    g_cd[BT_];
__device__ float    g_hd[BT_];
__device__ unsigned g_done;

// ---------------------------------------------------------------------------
__device__ __forceinline__ unsigned enc_desc(float f) {
    unsigned b = __float_as_uint(f);
    unsigned asc = (b & 0x80000000u) ? ~b : (b | 0x80000000u);
    return ~asc;
}
__device__ __forceinline__ float dec_desc(unsigned k) {
    unsigned asc = ~k;
    unsigned b = (asc & 0x80000000u) ? (asc ^ 0x80000000u) : ~asc;
    return __uint_as_float(b);
}

typedef unsigned long long u64;
__device__ __forceinline__ u64 fma2(u64 a, u64 b, u64 c) {
    u64 d; asm("fma.rn.f32x2 %0, %1, %2, %3;" : "=l"(d) : "l"(a), "l"(b), "l"(c));
    return d;
}
__device__ __forceinline__ u64 add2(u64 a, u64 b) {
    u64 d; asm("add.rn.f32x2 %0, %1, %2;" : "=l"(d) : "l"(a), "l"(b));
    return d;
}
__device__ __forceinline__ u64 pack2(float a, float b) {
    u64 r; asm("mov.b64 %0, {%1, %2};" : "=l"(r) : "f"(a), "f"(b));
    return r;
}
__device__ __forceinline__ void unpack2(u64 v, float& a, float& b) {
    asm("mov.b64 {%0, %1}, %2;" : "=f"(a), "=f"(b) : "l"(v));
}

__device__ __forceinline__ bool ldmask(const void* p, int i, int mode) {
    if (mode == 0) return ((const unsigned char*)p)[i] != 0;
    if (mode == 1) return ((const int*)p)[i] != 0;
    return ((const float*)p)[i] != 0.0f;
}

// Per-block mask-dtype detection (warp-0 ballot of 32 samples of the ~95%-
// dense padding mask). P(all 32 sampled bytes zero for u8 bool) ~ 0.05^32.
__device__ __forceinline__ int detect_mode_block(const unsigned char* pad,
                                                 int tid, int* s_mode) {
    if (tid < 32) {
        const unsigned b1 = __ballot_sync(0xffffffffu, pad[4 * tid + 1] != 0);
        const unsigned b2 = __ballot_sync(0xffffffffu, pad[4 * tid + 2] != 0);
        if (tid == 0) *s_mode = b1 ? 0 : (b2 ? 2 : 1);
    }
    __syncthreads();
    return *s_mode;
}

// ---------------------------------------------------------------------------
// dist: grid (ROWBLKS, COLBLKS, BT_*2), 128 threads.
// ---------------------------------------------------------------------------
__global__ void __launch_bounds__(128) dist_kernel(
    const float* __restrict__ pred, const float* __restrict__ tgt,
    const void* __restrict__ isctl, const void* __restrict__ pad,
    const void* __restrict__ vis)
{
    // allow the dependent (epilogue) grid to start launching
    asm volatile("griddepcontrol.launch_dependents;");

    __shared__ float4 sc[COLS_PB * 2];  // per col: (-2x,-2x,-2y,-2y)(-2z,-2z,w,w)
    __shared__ int    s_mode;

    const int rowblk = blockIdx.x;
    const int colblk = blockIdx.y;
    const int bt     = blockIdx.z >> 1;
    const int pass   = blockIdx.z & 1;
    const int b      = bt >> 2;
    const int tid    = threadIdx.x;
    const int mode   = detect_mode_block((const unsigned char*)pad, tid, &s_mode);

    const float* __restrict__ rows = pass ? tgt  : pred;
    const float* __restrict__ cols = pass ? pred : tgt;
    unsigned* __restrict__ enc = pass ? &g_enc_t[bt][0] : &g_enc_p[bt][0];

    // ---- stage this block's 512 columns (once) -----------------------------
#pragma unroll
    for (int c = tid; c < COLS_PB; c += 128) {
        const int m = colblk * COLS_PB + c;
        const float* cp = cols + ((size_t)bt * N_ + m) * 3;
        const float x = cp[0], y = cp[1], z = cp[2];
        const bool msk = !ldmask(isctl, b * N_ + m, mode)
                       &&  ldmask(pad,   b * N_ + m, mode)
                       &&  ldmask(vis,  bt * N_ + m, mode);
        const float cw = fmaf(x, x, fmaf(y, y, z * z)) + (msk ? 0.0f : BIGF);
        sc[2 * c]     = make_float4(-2.f * x, -2.f * x, -2.f * y, -2.f * y);
        sc[2 * c + 1] = make_float4(-2.f * z, -2.f * z, cw, cw);
    }

    // ---- this thread's 8 rows (4 packed pairs) -----------------------------
    u64 px2[4], py2[4], pz2[4], rw2[4];
    float rmin[RPT];
    const int rbase = rowblk * ROWS_PB + tid * RPT;
#pragma unroll
    for (int q = 0; q < 4; q++) {
        float x[2], y[2], z[2], w[2];
#pragma unroll
        for (int h = 0; h < 2; h++) {
            const int row = rbase + q * 2 + h;
            const float* rp = rows + ((size_t)bt * N_ + row) * 3;
            x[h] = rp[0]; y[h] = rp[1]; z[h] = rp[2];
            const bool msk = !ldmask(isctl, b * N_ + row, mode)
                           &&  ldmask(pad,   b * N_ + row, mode)
                           &&  ldmask(vis,  bt * N_ + row, mode);
            w[h] = fmaf(x[h], x[h], fmaf(y[h], y[h], z[h] * z[h]))
                 + (msk ? 0.0f : BIGF);
            rmin[q * 2 + h] = 3.0e38f;
        }
        px2[q] = pack2(x[0], x[1]);
        py2[q] = pack2(y[0], y[1]);
        pz2[q] = pack2(z[0], z[1]);
        rw2[q] = pack2(w[0], w[1]);
    }
    __syncthreads();   // the only barrier

    // ---- pure streaming loop: 512 cols x 8 rows ----------------------------
#pragma unroll 2
    for (int c = 0; c < COLS_PB; c++) {
        const u64* cd = reinterpret_cast<const u64*>(&sc[2 * c]);
        const u64 xd = cd[0], yd = cd[1], zd = cd[2], wd = cd[3];
#pragma unroll
        for (int q = 0; q < 4; q++) {
            const u64 acc = fma2(px2[q], xd,
                            fma2(py2[q], yd,
                            fma2(pz2[q], zd, add2(wd, rw2[q]))));
            float lo, hi;
            unpack2(acc, lo, hi);
            rmin[q * 2]     = fminf(rmin[q * 2], lo);
            rmin[q * 2 + 1] = fminf(rmin[q * 2 + 1], hi);
        }
    }

    // ---- publish 8 row-mins (thread-exclusive rows, 8 colblk contenders) ---
#pragma unroll
    for (int r = 0; r < RPT; r++)
        atomicMax(&enc[rbase + r], enc_desc(rmin[r]));
}

// ---------------------------------------------------------------------------
// epilogue (PDL dependent): grid=8 (bt), 1024 threads.
// Preamble (mode detect + mask loads) BEFORE griddepcontrol.wait.
// ---------------------------------------------------------------------------
__device__ __forceinline__ float blockRed1024(float v, float* s, bool ismax) {
    const int w = threadIdx.x >> 5, l = threadIdx.x & 31;
#pragma unroll
    for (int o = 16; o > 0; o >>= 1) {
        const float x = __shfl_xor_sync(0xffffffffu, v, o);
        v = ismax ? fmaxf(v, x) : (v + x);
    }
    __syncthreads();
    if (l == 0) s[w] = v;
    __syncthreads();
    if (w == 0) {
        v = s[l];
#pragma unroll
        for (int o = 16; o > 0; o >>= 1) {
            const float x = __shfl_xor_sync(0xffffffffu, v, o);
            v = ismax ? fmaxf(v, x) : (v + x);
        }
        if (l == 0) s[0] = v;
    }
    __syncthreads();
    const float r = s[0];
    __syncthreads();
    return r;
}

__global__ void __launch_bounds__(1024) epilogue_kernel(
    const void* __restrict__ isctl, const void* __restrict__ pad,
    const void* __restrict__ vis, float* __restrict__ out)
{
    __shared__ float s[32];
    __shared__ int   s_mode;
    const int bt   = blockIdx.x;
    const int b    = bt >> 2;
    const int tid  = threadIdx.x;
    constexpr int K = N_ / 1024;   // 4

    // ---------- preamble: everything independent of dist output ------------
    const int mode = detect_mode_block((const unsigned char*)pad, tid, &s_mode);
    bool mk[K];
#pragma unroll
    for (int k = 0; k < K; k++) {
        const int n = tid + k * 1024;
        mk[k] = !ldmask(isctl, b * N_ + n, mode)
              &&  ldmask(pad,   b * N_ + n, mode)
              &&  ldmask(vis,  bt * N_ + n, mode);
    }

    // ---------- wait for dist grid completion (memory visible) -------------
    asm volatile("griddepcontrol.wait;" ::: "memory");

    float hp[K], ht[K];
    float nv = 0.f, cdp = 0.f, cdt = 0.f;
    float mxp = -3.0e38f, mxt = -3.0e38f;
#pragma unroll
    for (int k = 0; k < K; k++) {
        const int n = tid + k * 1024;
        const float mp = fmaxf(dec_desc(g_enc_p[bt][n]), 0.0f);
        const float mt = fmaxf(dec_desc(g_enc_t[bt][n]), 0.0f);
        g_enc_p[bt][n] = 0u;                  // clean for next call
        g_enc_t[bt][n] = 0u;
        if (mk[k]) {
            nv  += 1.0f;
            cdp += (mp > THRESHF) ? 0.0f : mp;
            cdt += (mt > THRESHF) ? 0.0f : mt;
            hp[k] = fminf(mp, THRESHF);
            ht[k] = fminf(mt, THRESHF);
            mxp = fmaxf(mxp, hp[k]);
            mxt = fmaxf(mxt, ht[k]);
        } else { hp[k] = 0.f; ht[k] = 0.f; }
    }

    const float nvT  = blockRed1024(nv,  s, false);
    const float cdpT = blockRed1024(cdp, s, false);
    const float cdtT = blockRed1024(cdt, s, false);
    const float Mp   = blockRed1024(mxp, s, true);
    const float Mt   = blockRed1024(mxt, s, true);
    const bool  anyv = (Mp > -1.0e30f);

    float sep = 0.f, shp = 0.f, set = 0.f, sht = 0.f;
#pragma unroll
    for (int k = 0; k < K; k++) {
        if (mk[k]) {
            const float e1 = expf((hp[k] - Mp) * INV_TEMP);
            const float e2 = expf((ht[k] - Mt) * INV_TEMP);
            sep += e1; shp += hp[k] * e1;
            set += e2; sht += ht[k] * e2;
        }
    }
    const float sepT = blockRed1024(sep, s, false);
    const float shpT = blockRed1024(shp, s, false);
    const float setT = blockRed1024(set, s, false);
    const float shtT = blockRed1024(sht, s, false);

    if (tid == 0) {
        const float nvc = fmaxf(nvT, 1.0f);
        g_cd[bt] = cdpT / nvc + cdtT / nvc;
        const float rp = anyv ? (shpT / sepT) : 0.0f;
        const float rt = anyv ? (shtT / setT) : 0.0f;
        g_hd[bt] = fmaxf(rp, rt);
        __threadfence();
        const unsigned rank = atomicAdd(&g_done, 1u);
        if (rank == BT_ - 1) {                // last block: fixed-order combine
            __threadfence();
            float cd = 0.f, hd = 0.f;
#pragma unroll
            for (int i = 0; i < BT_; i++) { cd += g_cd[i]; hd += g_hd[i]; }
            out[0] = ALPHA_C * (cd / (float)BT_)
                   + (1.0f - ALPHA_C) * (hd / (float)BT_);
            g_done = 0u;                      // reset for next call
        }
    }
}

// ---------------------------------------------------------------------------
extern "C" void kernel_launch(void* const* d_in, const int* in_sizes, int n_in,
                              void* d_out, int out_size) {
    const float* pred = (const float*)d_in[0];
    const float* tgt  = (const float*)d_in[1];
    const void*  isc  = d_in[2];
    const void*  pad  = d_in[3];
    const void*  vis  = d_in[4];
    float*       out  = (float*)d_out;

    dist_kernel<<<dim3(ROWBLKS, COLBLKS, BT_ * 2), 128>>>(
        pred, tgt, isc, pad, vis);

    // PDL dependent launch: epilogue may start while dist drains; it gates
    // itself with griddepcontrol.wait before reading dist output.
    cudaLaunchConfig_t cfg = {};
    cfg.gridDim  = dim3(BT_);
    cfg.blockDim = dim3(1024);
    cudaLaunchAttribute attr[1];
    attr[0].id = cudaLaunchAttributeProgrammaticStreamSerialization;
    attr[0].val.programmaticStreamSerializationAllowed = 1;
    cfg.attrs = attr;
    cfg.numAttrs = 1;
    cudaLaunchKernelEx(&cfg, epilogue_kernel, isc, pad, vis, out);
}

// round 12
// speedup vs baseline: 1.7114x; 1.0482x over previous
#include <cuda_runtime.h>

// ============================================================================
// HybridLoss: B=2, T=4, N=4096  —  2 launches with PDL overlap.
// DIST (dual-pass, zero-shuffle): block = 1024 rows x 512 cols, 128 thr.
//   pass 0: rows=pred, cols=tgt  -> row-min = min_p -> g_enc_p
//   pass 1: rows=tgt,  cols=pred -> row-min = min_t -> g_enc_t
//   Row bias rw is row-constant -> added ONCE at publish (outside the loop):
//   hot loop = 3 fma2 + 2 FMNMX per 2 distances (1.5 fma-ops/dist).
// EPILOGUE: grid 8 x 1024 thr, PDL dependent (mask preamble before wait).
// All device state zero at load and re-zeroed each call (graph-safe).
// ============================================================================

#define ALPHA_C  0.5f
#define INV_TEMP 10.0f
#define BIGF     10000000000.0f
#define THRESHF  1000000000.0f

constexpr int N_  = 4096;
constexpr int BT_ = 8;

constexpr int ROWS_PB = 1024;             // rows per block
constexpr int COLS_PB = 512;              // cols per block (staged once)
constexpr int RPT     = 8;                // rows per thread (4 packed pairs)
constexpr int ROWBLKS = N_ / ROWS_PB;     // 4
constexpr int COLBLKS = N_ / COLS_PB;     // 8

__device__ unsigned g_enc_p[BT_][N_];
__device__ unsigned g_enc_t[BT_][N_];
__device__ float    g_cd[BT_];
__device__ float    g_hd[BT_];
__device__ unsigned g_done;

// ---------------------------------------------------------------------------
__device__ __forceinline__ unsigned enc_desc(float f) {
    unsigned b = __float_as_uint(f);
    unsigned asc = (b & 0x80000000u) ? ~b : (b | 0x80000000u);
    return ~asc;
}
__device__ __forceinline__ float dec_desc(unsigned k) {
    unsigned asc = ~k;
    unsigned b = (asc & 0x80000000u) ? (asc ^ 0x80000000u) : ~asc;
    return __uint_as_float(b);
}

typedef unsigned long long u64;
__device__ __forceinline__ u64 fma2(u64 a, u64 b, u64 c) {
    u64 d; asm("fma.rn.f32x2 %0, %1, %2, %3;" : "=l"(d) : "l"(a), "l"(b), "l"(c));
    return d;
}
__device__ __forceinline__ u64 pack2(float a, float b) {
    u64 r; asm("mov.b64 %0, {%1, %2};" : "=l"(r) : "f"(a), "f"(b));
    return r;
}
__device__ __forceinline__ void unpack2(u64 v, float& a, float& b) {
    asm("mov.b64 {%0, %1}, %2;" : "=f"(a), "=f"(b) : "l"(v));
}

__device__ __forceinline__ bool ldmask(const void* p, int i, int mode) {
    if (mode == 0) return ((const unsigned char*)p)[i] != 0;
    if (mode == 1) return ((const int*)p)[i] != 0;
    return ((const float*)p)[i] != 0.0f;
}

// Per-block mask-dtype detection (warp-0 ballot of 32 samples of the ~95%-
// dense padding mask). P(all 32 sampled bytes zero for u8 bool) ~ 0.05^32.
__device__ __forceinline__ int detect_mode_block(const unsigned char* pad,
                                                 int tid, int* s_mode) {
    if (tid < 32) {
        const unsigned b1 = __ballot_sync(0xffffffffu, pad[4 * tid + 1] != 0);
        const unsigned b2 = __ballot_sync(0xffffffffu, pad[4 * tid + 2] != 0);
        if (tid == 0) *s_mode = b1 ? 0 : (b2 ? 2 : 1);
    }
    __syncthreads();
    return *s_mode;
}

// ---------------------------------------------------------------------------
// dist: grid (ROWBLKS, COLBLKS, BT_*2), 128 threads.
// ---------------------------------------------------------------------------
__global__ void __launch_bounds__(128) dist_kernel(
    const float* __restrict__ pred, const float* __restrict__ tgt,
    const void* __restrict__ isctl, const void* __restrict__ pad,
    const void* __restrict__ vis)
{
    // allow the dependent (epilogue) grid to start launching
    asm volatile("griddepcontrol.launch_dependents;");

    __shared__ float4 sc[COLS_PB * 2];  // per col: (-2x,-2x,-2y,-2y)(-2z,-2z,w,w)
    __shared__ int    s_mode;

    const int rowblk = blockIdx.x;
    const int colblk = blockIdx.y;
    const int bt     = blockIdx.z >> 1;
    const int pass   = blockIdx.z & 1;
    const int b      = bt >> 2;
    const int tid    = threadIdx.x;
    const int mode   = detect_mode_block((const unsigned char*)pad, tid, &s_mode);

    const float* __restrict__ rows = pass ? tgt  : pred;
    const float* __restrict__ cols = pass ? pred : tgt;
    unsigned* __restrict__ enc = pass ? &g_enc_t[bt][0] : &g_enc_p[bt][0];

    // ---- stage this block's 512 columns (once) -----------------------------
#pragma unroll
    for (int c = tid; c < COLS_PB; c += 128) {
        const int m = colblk * COLS_PB + c;
        const float* cp = cols + ((size_t)bt * N_ + m) * 3;
        const float x = cp[0], y = cp[1], z = cp[2];
        const bool msk = !ldmask(isctl, b * N_ + m, mode)
                       &&  ldmask(pad,   b * N_ + m, mode)
                       &&  ldmask(vis,  bt * N_ + m, mode);
        const float cw = fmaf(x, x, fmaf(y, y, z * z)) + (msk ? 0.0f : BIGF);
        sc[2 * c]     = make_float4(-2.f * x, -2.f * x, -2.f * y, -2.f * y);
        sc[2 * c + 1] = make_float4(-2.f * z, -2.f * z, cw, cw);
    }

    // ---- this thread's 8 rows (4 packed pairs); rw deferred to publish -----
    u64 px2[4], py2[4], pz2[4];
    float rw[RPT], rmin[RPT];
    const int rbase = rowblk * ROWS_PB + tid * RPT;
#pragma unroll
    for (int q = 0; q < 4; q++) {
        float x[2], y[2], z[2];
#pragma unroll
        for (int h = 0; h < 2; h++) {
            const int row = rbase + q * 2 + h;
            const float* rp = rows + ((size_t)bt * N_ + row) * 3;
            x[h] = rp[0]; y[h] = rp[1]; z[h] = rp[2];
            const bool msk = !ldmask(isctl, b * N_ + row, mode)
                           &&  ldmask(pad,   b * N_ + row, mode)
                           &&  ldmask(vis,  bt * N_ + row, mode);
            rw[q * 2 + h] = fmaf(x[h], x[h], fmaf(y[h], y[h], z[h] * z[h]))
                          + (msk ? 0.0f : BIGF);
            rmin[q * 2 + h] = 3.0e38f;
        }
        px2[q] = pack2(x[0], x[1]);
        py2[q] = pack2(y[0], y[1]);
        pz2[q] = pack2(z[0], z[1]);
    }
    __syncthreads();   // the only barrier

    // ---- pure streaming loop: 512 cols x 8 rows, 3 fma2 + 2 min / 2 dists --
#pragma unroll 4
    for (int c = 0; c < COLS_PB; c++) {
        const u64* cd = reinterpret_cast<const u64*>(&sc[2 * c]);
        const u64 xd = cd[0], yd = cd[1], zd = cd[2], wd = cd[3];
#pragma unroll
        for (int q = 0; q < 4; q++) {
            const u64 acc = fma2(px2[q], xd,
                            fma2(py2[q], yd,
                            fma2(pz2[q], zd, wd)));
            float lo, hi;
            unpack2(acc, lo, hi);
            rmin[q * 2]     = fminf(rmin[q * 2], lo);
            rmin[q * 2 + 1] = fminf(rmin[q * 2 + 1], hi);
        }
    }

    // ---- publish 8 row-mins (row bias added once, outside the loop) --------
#pragma unroll
    for (int r = 0; r < RPT; r++)
        atomicMax(&enc[rbase + r], enc_desc(rmin[r] + rw[r]));
}

// ---------------------------------------------------------------------------
// epilogue (PDL dependent): grid=8 (bt), 1024 threads.
// Preamble (mode detect + mask loads) BEFORE griddepcontrol.wait.
// ---------------------------------------------------------------------------
__device__ __forceinline__ float blockRed1024(float v, float* s, bool ismax) {
    const int w = threadIdx.x >> 5, l = threadIdx.x & 31;
#pragma unroll
    for (int o = 16; o > 0; o >>= 1) {
        const float x = __shfl_xor_sync(0xffffffffu, v, o);
        v = ismax ? fmaxf(v, x) : (v + x);
    }
    __syncthreads();
    if (l == 0) s[w] = v;
    __syncthreads();
    if (w == 0) {
        v = s[l];
#pragma unroll
        for (int o = 16; o > 0; o >>= 1) {
            const float x = __shfl_xor_sync(0xffffffffu, v, o);
            v = ismax ? fmaxf(v, x) : (v + x);
        }
        if (l == 0) s[0] = v;
    }
    __syncthreads();
    const float r = s[0];
    __syncthreads();
    return r;
}

__global__ void __launch_bounds__(1024) epilogue_kernel(
    const void* __restrict__ isctl, const void* __restrict__ pad,
    const void* __restrict__ vis, float* __restrict__ out)
{
    __shared__ float s[32];
    __shared__ int   s_mode;
    const int bt   = blockIdx.x;
    const int b    = bt >> 2;
    const int tid  = threadIdx.x;
    constexpr int K = N_ / 1024;   // 4

    // ---------- preamble: everything independent of dist output ------------
    const int mode = detect_mode_block((const unsigned char*)pad, tid, &s_mode);
    bool mk[K];
#pragma unroll
    for (int k = 0; k < K; k++) {
        const int n = tid + k * 1024;
        mk[k] = !ldmask(isctl, b * N_ + n, mode)
              &&  ldmask(pad,   b * N_ + n, mode)
              &&  ldmask(vis,  bt * N_ + n, mode);
    }

    // ---------- wait for dist grid completion (memory visible) -------------
    asm volatile("griddepcontrol.wait;" ::: "memory");

    float hp[K], ht[K];
    float nv = 0.f, cdp = 0.f, cdt = 0.f;
    float mxp = -3.0e38f, mxt = -3.0e38f;
#pragma unroll
    for (int k = 0; k < K; k++) {
        const int n = tid + k * 1024;
        const float mp = fmaxf(dec_desc(g_enc_p[bt][n]), 0.0f);
        const float mt = fmaxf(dec_desc(g_enc_t[bt][n]), 0.0f);
        g_enc_p[bt][n] = 0u;                  // clean for next call
        g_enc_t[bt][n] = 0u;
        if (mk[k]) {
            nv  += 1.0f;
            cdp += (mp > THRESHF) ? 0.0f : mp;
            cdt += (mt > THRESHF) ? 0.0f : mt;
            hp[k] = fminf(mp, THRESHF);
            ht[k] = fminf(mt, THRESHF);
            mxp = fmaxf(mxp, hp[k]);
            mxt = fmaxf(mxt, ht[k]);
        } else { hp[k] = 0.f; ht[k] = 0.f; }
    }

    const float nvT  = blockRed1024(nv,  s, false);
    const float cdpT = blockRed1024(cdp, s, false);
    const float cdtT = blockRed1024(cdt, s, false);
    const float Mp   = blockRed1024(mxp, s, true);
    const float Mt   = blockRed1024(mxt, s, true);
    const bool  anyv = (Mp > -1.0e30f);

    float sep = 0.f, shp = 0.f, set = 0.f, sht = 0.f;
#pragma unroll
    for (int k = 0; k < K; k++) {
        if (mk[k]) {
            const float e1 = expf((hp[k] - Mp) * INV_TEMP);
            const float e2 = expf((ht[k] - Mt) * INV_TEMP);
            sep += e1; shp += hp[k] * e1;
            set += e2; sht += ht[k] * e2;
        }
    }
    const float sepT = blockRed1024(sep, s, false);
    const float shpT = blockRed1024(shp, s, false);
    const float setT = blockRed1024(set, s, false);
    const float shtT = blockRed1024(sht, s, false);

    if (tid == 0) {
        const float nvc = fmaxf(nvT, 1.0f);
        g_cd[bt] = cdpT / nvc + cdtT / nvc;
        const float rp = anyv ? (shpT / sepT) : 0.0f;
        const float rt = anyv ? (shtT / setT) : 0.0f;
        g_hd[bt] = fmaxf(rp, rt);
        __threadfence();
        const unsigned rank = atomicAdd(&g_done, 1u);
        if (rank == BT_ - 1) {                // last block: fixed-order combine
            __threadfence();
            float cd = 0.f, hd = 0.f;
#pragma unroll
            for (int i = 0; i < BT_; i++) { cd += g_cd[i]; hd += g_hd[i]; }
            out[0] = ALPHA_C * (cd / (float)BT_)
                   + (1.0f - ALPHA_C) * (hd / (float)BT_);
            g_done = 0u;                      // reset for next call
        }
    }
}

// ---------------------------------------------------------------------------
extern "C" void kernel_launch(void* const* d_in, const int* in_sizes, int n_in,
                              void* d_out, int out_size) {
    const float* pred = (const float*)d_in[0];
    const float* tgt  = (const float*)d_in[1];
    const void*  isc  = d_in[2];
    const void*  pad  = d_in[3];
    const void*  vis  = d_in[4];
    float*       out  = (float*)d_out;

    dist_kernel<<<dim3(ROWBLKS, COLBLKS, BT_ * 2), 128>>>(
        pred, tgt, isc, pad, vis);

    // PDL dependent launch: epilogue may start while dist drains; it gates
    // itself with griddepcontrol.wait before reading dist output.
    cudaLaunchConfig_t cfg = {};
    cfg.gridDim  = dim3(BT_);
    cfg.blockDim = dim3(1024);
    cudaLaunchAttribute attr[1];
    attr[0].id = cudaLaunchAttributeProgrammaticStreamSerialization;
    attr[0].val.programmaticStreamSerializationAllowed = 1;
    cfg.attrs = attr;
    cfg.numAttrs = 1;
    cudaLaunchKernelEx(&cfg, epilogue_kernel, isc, pad, vis, out);
}